// round 5
// baseline (speedup 1.0000x reference)
#include <cuda_runtime.h>
#include <cuda_fp16.h>

#define NN 50000
#define EE 800000
#define F  64
#define NG 64
#define NCHUNK 8192

// ---------------- scratch (device globals) ----------------------------------
__device__ float  g_dinv_in [NN];
__device__ float  g_dinv_out[NN];
__device__ __half g_pinh [NN * F];
__device__ __half g_pouth[NN * F];
__device__ float  g_h    [NN * F];
__device__ float  g_pool [NG * F];
__device__ float  g_cnt  [NG];

__device__ int g_cntin [NN];
__device__ int g_cntout[NN];
__device__ int g_offin [NN + 1];
__device__ int g_offout[NN + 1];
__device__ int g_curin [NN];
__device__ int g_curout[NN];
__device__ int g_csrin [EE];
__device__ int g_csrout[EE];
__device__ int g_sumin [NCHUNK];
__device__ int g_sumout[NCHUNK];
__device__ int g_cb2in [NCHUNK];
__device__ int g_cb2out[NCHUNK];

__device__ __forceinline__ unsigned h2_as_u(__half2 h) {
    return *reinterpret_cast<unsigned*>(&h);
}
__device__ __forceinline__ __half2 u_as_h2(unsigned u) {
    return *reinterpret_cast<__half2*>(&u);
}

// ---------------- init -------------------------------------------------------
__global__ void k_init(int n) {
    int t = blockIdx.x * blockDim.x + threadIdx.x;
    if (t < n) { g_cntin[t] = 0; g_cntout[t] = 0; }
    if (t < NG * F) g_pool[t] = 0.0f;
    if (t < NG) g_cnt[t] = 0.0f;
}

// ---------------- degree histogram: 4 edges per thread ----------------------
__global__ void k_count(const int* __restrict__ src, const int* __restrict__ dst, int e) {
    int t = blockIdx.x * blockDim.x + threadIdx.x;
    int i = t * 4;
    if (i + 3 < e) {
        int4 s4 = ((const int4*)src)[t];
        int4 d4 = ((const int4*)dst)[t];
        atomicAdd(&g_cntin[d4.x], 1); atomicAdd(&g_cntout[s4.x], 1);
        atomicAdd(&g_cntin[d4.y], 1); atomicAdd(&g_cntout[s4.y], 1);
        atomicAdd(&g_cntin[d4.z], 1); atomicAdd(&g_cntout[s4.z], 1);
        atomicAdd(&g_cntin[d4.w], 1); atomicAdd(&g_cntout[s4.w], 1);
    } else {
        for (; i < e; i++) {
            atomicAdd(&g_cntin[dst[i]], 1);
            atomicAdd(&g_cntout[src[i]], 1);
        }
    }
}

// ---------------- scan level 1: per-chunk sums (8192 chunks) ----------------
__global__ void k_chunksum(int n) {
    int t = blockIdx.x * blockDim.x + threadIdx.x;   // 8192 threads
    int C = (n + NCHUNK - 1) / NCHUNK;
    int s0 = t * C, s1 = min(n, s0 + C);
    int sa = 0, sb = 0;
    for (int i = s0; i < s1; i++) { sa += g_cntin[i]; sb += g_cntout[i]; }
    g_sumin[t] = sa; g_sumout[t] = sb;
}

// ---------------- scan level 2: single block over 8192 chunk sums -----------
__global__ __launch_bounds__(1024) void k_scanmid(int n) {
    __shared__ int pa[1024];
    __shared__ int pb[1024];
    int tid = threadIdx.x;
    int sa[8], sb[8];
    int suma = 0, sumb = 0;
    #pragma unroll
    for (int i = 0; i < 8; i++) {
        sa[i] = g_sumin [tid * 8 + i]; suma += sa[i];
        sb[i] = g_sumout[tid * 8 + i]; sumb += sb[i];
    }
    pa[tid] = suma; pb[tid] = sumb;
    __syncthreads();
    for (int off = 1; off < 1024; off <<= 1) {
        int a = (tid >= off) ? pa[tid - off] : 0;
        int b = (tid >= off) ? pb[tid - off] : 0;
        __syncthreads();
        pa[tid] += a; pb[tid] += b;
        __syncthreads();
    }
    int runa = pa[tid] - suma, runb = pb[tid] - sumb;
    #pragma unroll
    for (int i = 0; i < 8; i++) {
        g_cb2in [tid * 8 + i] = runa; runa += sa[i];
        g_cb2out[tid * 8 + i] = runb; runb += sb[i];
    }
    if (tid == 1023) { g_offin[n] = pa[1023]; g_offout[n] = pb[1023]; }
}

// ---------------- scan level 3: writeback + dinv (8192 threads) -------------
__global__ void k_scanB(int n) {
    int t = blockIdx.x * blockDim.x + threadIdx.x;
    int C = (n + NCHUNK - 1) / NCHUNK;
    int s0 = t * C, s1 = min(n, s0 + C);
    int runa = g_cb2in[t], runb = g_cb2out[t];
    for (int i = s0; i < s1; i++) {
        int ca = g_cntin[i], cb = g_cntout[i];
        g_offin [i] = runa; g_curin [i] = runa; runa += ca;
        g_offout[i] = runb; g_curout[i] = runb; runb += cb;
        g_dinv_in [i] = rsqrtf(1.0f + (float)ca);
        g_dinv_out[i] = rsqrtf(1.0f + (float)cb);
    }
}

// ---------------- CSR placement: 4 edges per thread -------------------------
__global__ void k_place(const int* __restrict__ src, const int* __restrict__ dst, int e) {
    int t = blockIdx.x * blockDim.x + threadIdx.x;
    int i = t * 4;
    if (i + 3 < e) {
        int4 s4 = ((const int4*)src)[t];
        int4 d4 = ((const int4*)dst)[t];
        int p0 = atomicAdd(&g_curin [d4.x], 1);
        int p1 = atomicAdd(&g_curin [d4.y], 1);
        int p2 = atomicAdd(&g_curin [d4.z], 1);
        int p3 = atomicAdd(&g_curin [d4.w], 1);
        g_csrin[p0] = s4.x; g_csrin[p1] = s4.y; g_csrin[p2] = s4.z; g_csrin[p3] = s4.w;
        int q0 = atomicAdd(&g_curout[s4.x], 1);
        int q1 = atomicAdd(&g_curout[s4.y], 1);
        int q2 = atomicAdd(&g_curout[s4.z], 1);
        int q3 = atomicAdd(&g_curout[s4.w], 1);
        g_csrout[q0] = d4.x; g_csrout[q1] = d4.y; g_csrout[q2] = d4.z; g_csrout[q3] = d4.w;
    } else {
        for (; i < e; i++) {
            int s = src[i], d = dst[i];
            int p = atomicAdd(&g_curin [d], 1); g_csrin [p] = s;
            int q = atomicAdd(&g_curout[s], 1); g_csrout[q] = d;
        }
    }
}

// ---------------- fused dual GEMM + dinv pre-scale, fp16 output ------------
__global__ __launch_bounds__(256) void k_gemm(const float* __restrict__ xin,
                                              const float* __restrict__ Win,
                                              const float* __restrict__ Wout,
                                              int n) {
    __shared__ float xs[64 * 64];
    __shared__ float wi[64 * 64];
    __shared__ float wo[64 * 64];
    const float* x = xin ? xin : g_h;

    int tid = threadIdx.x;
    {
        float4* wi4 = (float4*)wi; const float4* Wi4 = (const float4*)Win;
        float4* wo4 = (float4*)wo; const float4* Wo4 = (const float4*)Wout;
        #pragma unroll
        for (int i = tid; i < 1024; i += 256) { wi4[i] = Wi4[i]; wo4[i] = Wo4[i]; }
    }
    int base = blockIdx.x * 64;
    {
        const float4* x4 = (const float4*)x;
        #pragma unroll
        for (int i = tid; i < 1024; i += 256) {
            int r = i >> 4;
            int row = base + r;
            ((float4*)xs)[i] = (row < n) ? x4[row * 16 + (i & 15)]
                                         : make_float4(0.f, 0.f, 0.f, 0.f);
        }
    }
    __syncthreads();

    int fq = tid & 15;
    int rg = tid >> 4;
    int r0 = rg * 4;

    float4 ai[4], ao[4];
    #pragma unroll
    for (int r = 0; r < 4; r++) {
        ai[r] = make_float4(0.f, 0.f, 0.f, 0.f);
        ao[r] = make_float4(0.f, 0.f, 0.f, 0.f);
    }
    const float4* wi4 = (const float4*)wi;
    const float4* wo4 = (const float4*)wo;
    #pragma unroll
    for (int k = 0; k < 64; k++) {
        float4 a = wi4[k * 16 + fq];
        float4 b = wo4[k * 16 + fq];
        #pragma unroll
        for (int r = 0; r < 4; r++) {
            float xk = xs[(r0 + r) * 64 + k];
            ai[r].x += xk * a.x; ai[r].y += xk * a.y; ai[r].z += xk * a.z; ai[r].w += xk * a.w;
            ao[r].x += xk * b.x; ao[r].y += xk * b.y; ao[r].z += xk * b.z; ao[r].w += xk * b.w;
        }
    }
    #pragma unroll
    for (int r = 0; r < 4; r++) {
        int row = base + r0 + r;
        if (row >= n) break;
        float di = g_dinv_in[row], dq = g_dinv_out[row];
        __half2 pi0 = __float22half2_rn(make_float2(ai[r].x * di, ai[r].y * di));
        __half2 pi1 = __float22half2_rn(make_float2(ai[r].z * di, ai[r].w * di));
        __half2 po0 = __float22half2_rn(make_float2(ao[r].x * dq, ao[r].y * dq));
        __half2 po1 = __float22half2_rn(make_float2(ao[r].z * dq, ao[r].w * dq));
        uint2 ui, uo;
        ui.x = h2_as_u(pi0); ui.y = h2_as_u(pi1);
        uo.x = h2_as_u(po0); uo.y = h2_as_u(po1);
        ((uint2*)g_pinh )[row * 16 + fq] = ui;
        ((uint2*)g_pouth)[row * 16 + fq] = uo;
    }
}

// ---------------- gather: one warp/node, 4 edge-quarters, fp16 msgs ---------
__device__ __forceinline__ void acc8(float2 acc[4], uint4 v) {
    #pragma unroll
    for (int i = 0; i < 4; i++) {
        float2 f = __half22float2(u_as_h2(((const unsigned*)&v)[i]));
        acc[i].x += f.x; acc[i].y += f.y;
    }
}

__global__ __launch_bounds__(256) void k_gather(const float* __restrict__ bin,
                                                const float* __restrict__ bout,
                                                int n, int doRelu) {
    int v = (blockIdx.x * 256 + threadIdx.x) >> 5;
    if (v >= n) return;
    int lane = threadIdx.x & 31;
    int q  = lane >> 3;        // edge quarter 0..3
    int fl = lane & 7;         // uint4 group within row (8 per row)
    const uint4* pin4  = (const uint4*)g_pinh;
    const uint4* pout4 = (const uint4*)g_pouth;

    float2 a1[4], a2[4], b1[4], b2[4];
    #pragma unroll
    for (int i = 0; i < 4; i++) {
        a1[i] = make_float2(0.f, 0.f); a2[i] = make_float2(0.f, 0.f);
        b1[i] = make_float2(0.f, 0.f); b2[i] = make_float2(0.f, 0.f);
    }
    // self-loop seeds (quarter 0 only)
    if (q == 0) {
        acc8(a1, pin4 [v * 8 + fl]);
        acc8(b1, pout4[v * 8 + fl]);
    }

    // ---- in direction
    {
        int i0 = g_offin[v], i1 = g_offin[v + 1];
        for (int base = i0; base < i1; base += 32) {
            int cnt = min(32, i1 - base);
            int idx = 0;
            if (lane < cnt) idx = g_csrin[base + lane];
            for (int j = 0; j < cnt; j += 8) {
                int j1 = j + q, j2 = j + 4 + q;
                int s1 = __shfl_sync(0xffffffffu, idx, j1 & 31);
                int s2 = __shfl_sync(0xffffffffu, idx, j2 & 31);
                if (j1 < cnt) acc8(a1, pin4[s1 * 8 + fl]);
                if (j2 < cnt) acc8(a2, pin4[s2 * 8 + fl]);
            }
        }
    }
    // ---- out direction
    {
        int i0 = g_offout[v], i1 = g_offout[v + 1];
        for (int base = i0; base < i1; base += 32) {
            int cnt = min(32, i1 - base);
            int idx = 0;
            if (lane < cnt) idx = g_csrout[base + lane];
            for (int j = 0; j < cnt; j += 8) {
                int j1 = j + q, j2 = j + 4 + q;
                int s1 = __shfl_sync(0xffffffffu, idx, j1 & 31);
                int s2 = __shfl_sync(0xffffffffu, idx, j2 & 31);
                if (j1 < cnt) acc8(b1, pout4[s1 * 8 + fl]);
                if (j2 < cnt) acc8(b2, pout4[s2 * 8 + fl]);
            }
        }
    }

    // merge chains and reduce across quarters (xor 8, 16)
    float ain[8], aout[8];
    #pragma unroll
    for (int i = 0; i < 4; i++) {
        ain [2*i]   = a1[i].x + a2[i].x;  ain [2*i+1] = a1[i].y + a2[i].y;
        aout[2*i]   = b1[i].x + b2[i].x;  aout[2*i+1] = b1[i].y + b2[i].y;
    }
    #pragma unroll
    for (int i = 0; i < 8; i++) {
        ain [i] += __shfl_xor_sync(0xffffffffu, ain [i], 8);
        ain [i] += __shfl_xor_sync(0xffffffffu, ain [i], 16);
        aout[i] += __shfl_xor_sync(0xffffffffu, aout[i], 8);
        aout[i] += __shfl_xor_sync(0xffffffffu, aout[i], 16);
    }

    if (q == 0) {
        float di = g_dinv_in[v], dq = g_dinv_out[v];
        float4 bi0 = ((const float4*)bin )[2 * fl];
        float4 bi1 = ((const float4*)bin )[2 * fl + 1];
        float4 bo0 = ((const float4*)bout)[2 * fl];
        float4 bo1 = ((const float4*)bout)[2 * fl + 1];
        float bif[8] = {bi0.x, bi0.y, bi0.z, bi0.w, bi1.x, bi1.y, bi1.z, bi1.w};
        float bof[8] = {bo0.x, bo0.y, bo0.z, bo0.w, bo1.x, bo1.y, bo1.z, bo1.w};
        float r[8];
        #pragma unroll
        for (int i = 0; i < 8; i++) {
            r[i] = 0.5f * (aout[i] * dq + bof[i]) + 0.5f * (ain[i] * di + bif[i]);
            if (doRelu) r[i] = fmaxf(r[i], 0.f);
        }
        float4 r0 = make_float4(r[0], r[1], r[2], r[3]);
        float4 r1 = make_float4(r[4], r[5], r[6], r[7]);
        ((float4*)g_h)[v * 16 + 2 * fl]     = r0;
        ((float4*)g_h)[v * 16 + 2 * fl + 1] = r1;
    }
}

// ---------------- pooling -----------------------------------------------------
__global__ void k_pool(const int* __restrict__ batch, int n) {
    __shared__ float sm[NG * F];
    __shared__ float smc[NG];
    int tid = threadIdx.x;                 // 256
    for (int i = tid; i < NG * F; i += 256) sm[i] = 0.f;
    if (tid < NG) smc[tid] = 0.f;
    __syncthreads();

    int per = (n + gridDim.x - 1) / gridDim.x;
    int b0 = blockIdx.x * per;
    int b1 = min(n, b0 + per);
    for (int i = b0 * 64 + tid; i < b1 * 64; i += 256) {
        int node = i >> 6, f = i & 63;
        atomicAdd(&sm[batch[node] * 64 + f], g_h[i]);
    }
    for (int node = b0 + tid; node < b1; node += 256)
        atomicAdd(&smc[batch[node]], 1.0f);
    __syncthreads();

    for (int i = tid; i < NG * F; i += 256)
        if (sm[i] != 0.f) atomicAdd(&g_pool[i], sm[i]);
    if (tid < NG && smc[tid] != 0.f) atomicAdd(&g_cnt[tid], smc[tid]);
}

// ---------------- head: mean, LayerNorm, MLP ---------------------------------
__global__ void k_head(const float* __restrict__ lnw, const float* __restrict__ lnb,
                       const float* __restrict__ P1w, const float* __restrict__ P1b,
                       const float* __restrict__ P2w, const float* __restrict__ P2b,
                       float* __restrict__ out) {
    __shared__ float z [NG * F];
    __shared__ float h1[NG * 128];
    int tid = threadIdx.x;           // 128

    if (tid < NG) {
        int g = tid;
        float c = fmaxf(g_cnt[g], 1.0f);
        float inv = 1.0f / c;
        float mu = 0.f;
        for (int f = 0; f < 64; f++) mu += g_pool[g * 64 + f];
        mu *= inv * (1.0f / 64.0f);
        float var = 0.f;
        for (int f = 0; f < 64; f++) {
            float d = g_pool[g * 64 + f] * inv - mu;
            var += d * d;
        }
        var *= (1.0f / 64.0f);
        float rs = rsqrtf(var + 1e-5f);
        for (int f = 0; f < 64; f++)
            z[g * 64 + f] = (g_pool[g * 64 + f] * inv - mu) * rs * lnw[f] + lnb[f];
    }
    __syncthreads();

    for (int idx = tid; idx < NG * 128; idx += 128) {
        int g = idx >> 7, j = idx & 127;
        float s = P1b[j];
        for (int k = 0; k < 64; k++) s += z[g * 64 + k] * P1w[k * 128 + j];
        h1[idx] = fmaxf(s, 0.f);
    }
    __syncthreads();

    {
        int g = tid >> 1, o = tid & 1;
        float s = P2b[o];
        for (int j = 0; j < 128; j++) s += h1[g * 128 + j] * P2w[j * 2 + o];
        out[g * 2 + o] = s;
    }
}

// ---------------- launch -----------------------------------------------------
extern "C" void kernel_launch(void* const* d_in, const int* in_sizes, int n_in,
                              void* d_out, int out_size) {
    const float* x     = (const float*)d_in[0];
    const int*   src   = (const int*)  d_in[1];
    const int*   dst   = (const int*)  d_in[2];
    const int*   batch = (const int*)  d_in[3];
    const float* W1_in = (const float*)d_in[4];
    const float* b1_in = (const float*)d_in[5];
    const float* W1_out= (const float*)d_in[6];
    const float* b1_out= (const float*)d_in[7];
    const float* W2_in = (const float*)d_in[8];
    const float* b2_in = (const float*)d_in[9];
    const float* W2_out= (const float*)d_in[10];
    const float* b2_out= (const float*)d_in[11];
    const float* W3_in = (const float*)d_in[12];
    const float* b3_in = (const float*)d_in[13];
    const float* W3_out= (const float*)d_in[14];
    const float* b3_out= (const float*)d_in[15];
    const float* ln_w  = (const float*)d_in[16];
    const float* ln_b  = (const float*)d_in[17];
    const float* P1_w  = (const float*)d_in[18];
    const float* P1_b  = (const float*)d_in[19];
    const float* P2_w  = (const float*)d_in[20];
    const float* P2_b  = (const float*)d_in[21];
    float* out = (float*)d_out;

    int n = in_sizes[0] / 64;   // 50000
    int e = in_sizes[1];        // 800000

    int ib = (n + 255) / 256;
    int eb4 = ((e + 3) / 4 + 255) / 256;
    k_init    <<<ib, 256>>>(n);
    k_count   <<<eb4, 256>>>(src, dst, e);
    k_chunksum<<<NCHUNK / 256, 256>>>(n);
    k_scanmid <<<1, 1024>>>(n);
    k_scanB   <<<NCHUNK / 256, 256>>>(n);
    k_place   <<<eb4, 256>>>(src, dst, e);

    int gemmBlocks = (n + 63) / 64;
    int gathBlocks = (n * 32 + 255) / 256;

    // layer 1
    k_gemm  <<<gemmBlocks, 256>>>(x, W1_in, W1_out, n);
    k_gather<<<gathBlocks, 256>>>(b1_in, b1_out, n, 1);
    // layer 2
    k_gemm  <<<gemmBlocks, 256>>>(nullptr, W2_in, W2_out, n);
    k_gather<<<gathBlocks, 256>>>(b2_in, b2_out, n, 1);
    // layer 3
    k_gemm  <<<gemmBlocks, 256>>>(nullptr, W3_in, W3_out, n);
    k_gather<<<gathBlocks, 256>>>(b3_in, b3_out, n, 0);

    k_pool<<<128, 256>>>(batch, n);
    k_head<<<1, 128>>>(ln_w, ln_b, P1_w, P1_b, P2_w, P2_b, out);
}

// round 6
// speedup vs baseline: 1.1959x; 1.1959x over previous
#include <cuda_runtime.h>
#include <cuda_fp16.h>

#define NN 50000
#define EE 800000
#define F  64
#define NG 64

// ---------------- scratch (device globals) ----------------------------------
__device__ float  g_dinv_in [NN];
__device__ float  g_dinv_out[NN];
__device__ __half g_pinh [NN * F];
__device__ __half g_pouth[NN * F];
__device__ float  g_h    [NN * F];
__device__ float  g_pool [NG * F];
__device__ float  g_cnt  [NG];

__device__ int g_cntin [NN];
__device__ int g_cntout[NN];
__device__ int g_offin [NN];
__device__ int g_offout[NN];
__device__ int g_curin [NN];
__device__ int g_curout[NN];
__device__ int g_csrin [EE];
__device__ int g_csrout[EE];
__device__ int g_ctrin;
__device__ int g_ctrout;

__device__ __forceinline__ unsigned h2_as_u(__half2 h) {
    return *reinterpret_cast<unsigned*>(&h);
}
__device__ __forceinline__ __half2 u_as_h2(unsigned u) {
    return *reinterpret_cast<__half2*>(&u);
}

// ---------------- init -------------------------------------------------------
__global__ void k_init(int n) {
    int t = blockIdx.x * blockDim.x + threadIdx.x;
    if (t < n) { g_cntin[t] = 0; g_cntout[t] = 0; }
    if (t < NG * F) g_pool[t] = 0.0f;
    if (t < NG) g_cnt[t] = 0.0f;
    if (t == 0) { g_ctrin = 0; g_ctrout = 0; }
}

// ---------------- degree histogram: 4 edges per thread ----------------------
__global__ void k_count(const int* __restrict__ src, const int* __restrict__ dst, int e) {
    int t = blockIdx.x * blockDim.x + threadIdx.x;
    int i = t * 4;
    if (i + 3 < e) {
        int4 s4 = ((const int4*)src)[t];
        int4 d4 = ((const int4*)dst)[t];
        atomicAdd(&g_cntin[d4.x], 1); atomicAdd(&g_cntout[s4.x], 1);
        atomicAdd(&g_cntin[d4.y], 1); atomicAdd(&g_cntout[s4.y], 1);
        atomicAdd(&g_cntin[d4.z], 1); atomicAdd(&g_cntout[s4.z], 1);
        atomicAdd(&g_cntin[d4.w], 1); atomicAdd(&g_cntout[s4.w], 1);
    } else {
        for (; i < e; i++) {
            atomicAdd(&g_cntin[dst[i]], 1);
            atomicAdd(&g_cntout[src[i]], 1);
        }
    }
}

// ---------------- offsets: non-monotonic CSR ranges via block atomics -------
// Each node gets a disjoint contiguous range; order across blocks irrelevant.
__global__ __launch_bounds__(256) void k_offsets(int n) {
    __shared__ int wsa[8], wsb[8];
    __shared__ int basea, baseb;
    int t = blockIdx.x * 256 + threadIdx.x;
    int lane = threadIdx.x & 31;
    int wid  = threadIdx.x >> 5;

    int ca = (t < n) ? g_cntin [t] : 0;
    int cb = (t < n) ? g_cntout[t] : 0;

    // warp inclusive scan
    int pa = ca, pb = cb;
    #pragma unroll
    for (int o = 1; o < 32; o <<= 1) {
        int xa = __shfl_up_sync(0xffffffffu, pa, o);
        int xb = __shfl_up_sync(0xffffffffu, pb, o);
        if (lane >= o) { pa += xa; pb += xb; }
    }
    if (lane == 31) { wsa[wid] = pa; wsb[wid] = pb; }
    __syncthreads();

    if (wid == 0) {
        int va = (lane < 8) ? wsa[lane] : 0;
        int vb = (lane < 8) ? wsb[lane] : 0;
        int sa = va, sb = vb;
        #pragma unroll
        for (int o = 1; o < 8; o <<= 1) {
            int xa = __shfl_up_sync(0xffffffffu, sa, o);
            int xb = __shfl_up_sync(0xffffffffu, sb, o);
            if (lane >= o) { sa += xa; sb += xb; }
        }
        if (lane == 7) {
            basea = atomicAdd(&g_ctrin,  sa);
            baseb = atomicAdd(&g_ctrout, sb);
        }
        if (lane < 8) { wsa[lane] = sa - va; wsb[lane] = sb - vb; }
    }
    __syncthreads();

    if (t < n) {
        int offa = basea + wsa[wid] + (pa - ca);
        int offb = baseb + wsb[wid] + (pb - cb);
        g_offin [t] = offa; g_curin [t] = offa;
        g_offout[t] = offb; g_curout[t] = offb;
        g_dinv_in [t] = rsqrtf(1.0f + (float)ca);
        g_dinv_out[t] = rsqrtf(1.0f + (float)cb);
    }
}

// ---------------- CSR placement: 4 edges per thread -------------------------
__global__ void k_place(const int* __restrict__ src, const int* __restrict__ dst, int e) {
    int t = blockIdx.x * blockDim.x + threadIdx.x;
    int i = t * 4;
    if (i + 3 < e) {
        int4 s4 = ((const int4*)src)[t];
        int4 d4 = ((const int4*)dst)[t];
        int p0 = atomicAdd(&g_curin [d4.x], 1);
        int p1 = atomicAdd(&g_curin [d4.y], 1);
        int p2 = atomicAdd(&g_curin [d4.z], 1);
        int p3 = atomicAdd(&g_curin [d4.w], 1);
        g_csrin[p0] = s4.x; g_csrin[p1] = s4.y; g_csrin[p2] = s4.z; g_csrin[p3] = s4.w;
        int q0 = atomicAdd(&g_curout[s4.x], 1);
        int q1 = atomicAdd(&g_curout[s4.y], 1);
        int q2 = atomicAdd(&g_curout[s4.z], 1);
        int q3 = atomicAdd(&g_curout[s4.w], 1);
        g_csrout[q0] = d4.x; g_csrout[q1] = d4.y; g_csrout[q2] = d4.z; g_csrout[q3] = d4.w;
    } else {
        for (; i < e; i++) {
            int s = src[i], d = dst[i];
            int p = atomicAdd(&g_curin [d], 1); g_csrin [p] = s;
            int q = atomicAdd(&g_curout[s], 1); g_csrout[q] = d;
        }
    }
}

// ---------------- fused dual GEMM + dinv pre-scale, fp16 output ------------
__global__ __launch_bounds__(256) void k_gemm(const float* __restrict__ xin,
                                              const float* __restrict__ Win,
                                              const float* __restrict__ Wout,
                                              int n) {
    __shared__ float xs[64 * 64];
    __shared__ float wi[64 * 64];
    __shared__ float wo[64 * 64];
    const float* x = xin ? xin : g_h;

    int tid = threadIdx.x;
    {
        float4* wi4 = (float4*)wi; const float4* Wi4 = (const float4*)Win;
        float4* wo4 = (float4*)wo; const float4* Wo4 = (const float4*)Wout;
        #pragma unroll
        for (int i = tid; i < 1024; i += 256) { wi4[i] = Wi4[i]; wo4[i] = Wo4[i]; }
    }
    int base = blockIdx.x * 64;
    {
        const float4* x4 = (const float4*)x;
        #pragma unroll
        for (int i = tid; i < 1024; i += 256) {
            int r = i >> 4;
            int row = base + r;
            ((float4*)xs)[i] = (row < n) ? x4[row * 16 + (i & 15)]
                                         : make_float4(0.f, 0.f, 0.f, 0.f);
        }
    }
    __syncthreads();

    int fq = tid & 15;
    int rg = tid >> 4;
    int r0 = rg * 4;

    float4 ai[4], ao[4];
    #pragma unroll
    for (int r = 0; r < 4; r++) {
        ai[r] = make_float4(0.f, 0.f, 0.f, 0.f);
        ao[r] = make_float4(0.f, 0.f, 0.f, 0.f);
    }
    const float4* wi4 = (const float4*)wi;
    const float4* wo4 = (const float4*)wo;
    #pragma unroll
    for (int k = 0; k < 64; k++) {
        float4 a = wi4[k * 16 + fq];
        float4 b = wo4[k * 16 + fq];
        #pragma unroll
        for (int r = 0; r < 4; r++) {
            float xk = xs[(r0 + r) * 64 + k];
            ai[r].x += xk * a.x; ai[r].y += xk * a.y; ai[r].z += xk * a.z; ai[r].w += xk * a.w;
            ao[r].x += xk * b.x; ao[r].y += xk * b.y; ao[r].z += xk * b.z; ao[r].w += xk * b.w;
        }
    }
    #pragma unroll
    for (int r = 0; r < 4; r++) {
        int row = base + r0 + r;
        if (row >= n) break;
        float di = g_dinv_in[row], dq = g_dinv_out[row];
        __half2 pi0 = __float22half2_rn(make_float2(ai[r].x * di, ai[r].y * di));
        __half2 pi1 = __float22half2_rn(make_float2(ai[r].z * di, ai[r].w * di));
        __half2 po0 = __float22half2_rn(make_float2(ao[r].x * dq, ao[r].y * dq));
        __half2 po1 = __float22half2_rn(make_float2(ao[r].z * dq, ao[r].w * dq));
        uint2 ui, uo;
        ui.x = h2_as_u(pi0); ui.y = h2_as_u(pi1);
        uo.x = h2_as_u(po0); uo.y = h2_as_u(po1);
        ((uint2*)g_pinh )[row * 16 + fq] = ui;
        ((uint2*)g_pouth)[row * 16 + fq] = uo;
    }
}

// ---------------- gather: one warp/node, R3 structure, fp16 uint2 loads -----
__device__ __forceinline__ void acc4(float4& acc, uint2 v) {
    float2 f0 = __half22float2(u_as_h2(v.x));
    float2 f1 = __half22float2(u_as_h2(v.y));
    acc.x += f0.x; acc.y += f0.y; acc.z += f1.x; acc.w += f1.y;
}

__global__ __launch_bounds__(256) void k_gather(const float* __restrict__ bin,
                                                const float* __restrict__ bout,
                                                int n, int doRelu) {
    int v = (blockIdx.x * 256 + threadIdx.x) >> 5;
    if (v >= n) return;
    int lane = threadIdx.x & 31;
    int fq   = lane & 15;      // uint2 group within row (16 per row)
    int half = lane >> 4;
    const uint2* pin2  = (const uint2*)g_pinh;
    const uint2* pout2 = (const uint2*)g_pouth;

    // ---- in direction
    float4 a1 = make_float4(0.f, 0.f, 0.f, 0.f);
    float4 a2 = make_float4(0.f, 0.f, 0.f, 0.f);
    if (half == 0) acc4(a1, pin2[v * 16 + fq]);   // self-loop seed
    {
        int i0 = g_offin[v], i1 = i0 + g_cntin[v];
        for (int base = i0; base < i1; base += 32) {
            int cnt = min(32, i1 - base);
            int idx = 0;
            if (lane < cnt) idx = g_csrin[base + lane];
            for (int j = 0; j < cnt; j += 4) {
                int j1 = j + half, j2 = j + 2 + half;
                int s1 = __shfl_sync(0xffffffffu, idx, j1 & 31);
                int s2 = __shfl_sync(0xffffffffu, idx, j2 & 31);
                if (j1 < cnt) acc4(a1, pin2[s1 * 16 + fq]);
                if (j2 < cnt) acc4(a2, pin2[s2 * 16 + fq]);
            }
        }
    }
    float4 ain = make_float4(a1.x + a2.x, a1.y + a2.y, a1.z + a2.z, a1.w + a2.w);

    // ---- out direction
    float4 b1 = make_float4(0.f, 0.f, 0.f, 0.f);
    float4 b2 = make_float4(0.f, 0.f, 0.f, 0.f);
    if (half == 0) acc4(b1, pout2[v * 16 + fq]);
    {
        int i0 = g_offout[v], i1 = i0 + g_cntout[v];
        for (int base = i0; base < i1; base += 32) {
            int cnt = min(32, i1 - base);
            int idx = 0;
            if (lane < cnt) idx = g_csrout[base + lane];
            for (int j = 0; j < cnt; j += 4) {
                int j1 = j + half, j2 = j + 2 + half;
                int s1 = __shfl_sync(0xffffffffu, idx, j1 & 31);
                int s2 = __shfl_sync(0xffffffffu, idx, j2 & 31);
                if (j1 < cnt) acc4(b1, pout2[s1 * 16 + fq]);
                if (j2 < cnt) acc4(b2, pout2[s2 * 16 + fq]);
            }
        }
    }
    float4 aout = make_float4(b1.x + b2.x, b1.y + b2.y, b1.z + b2.z, b1.w + b2.w);

    // ---- reduce across halves
    ain.x  += __shfl_xor_sync(0xffffffffu, ain.x,  16);
    ain.y  += __shfl_xor_sync(0xffffffffu, ain.y,  16);
    ain.z  += __shfl_xor_sync(0xffffffffu, ain.z,  16);
    ain.w  += __shfl_xor_sync(0xffffffffu, ain.w,  16);
    aout.x += __shfl_xor_sync(0xffffffffu, aout.x, 16);
    aout.y += __shfl_xor_sync(0xffffffffu, aout.y, 16);
    aout.z += __shfl_xor_sync(0xffffffffu, aout.z, 16);
    aout.w += __shfl_xor_sync(0xffffffffu, aout.w, 16);

    if (half == 0) {
        float di = g_dinv_in[v], dq = g_dinv_out[v];
        float4 bi = ((const float4*)bin )[fq];
        float4 bo = ((const float4*)bout)[fq];
        float4 r;
        r.x = 0.5f * (aout.x * dq + bo.x) + 0.5f * (ain.x * di + bi.x);
        r.y = 0.5f * (aout.y * dq + bo.y) + 0.5f * (ain.y * di + bi.y);
        r.z = 0.5f * (aout.z * dq + bo.z) + 0.5f * (ain.z * di + bi.z);
        r.w = 0.5f * (aout.w * dq + bo.w) + 0.5f * (ain.w * di + bi.w);
        if (doRelu) {
            r.x = fmaxf(r.x, 0.f); r.y = fmaxf(r.y, 0.f);
            r.z = fmaxf(r.z, 0.f); r.w = fmaxf(r.w, 0.f);
        }
        ((float4*)g_h)[v * 16 + fq] = r;
    }
}

// ---------------- pooling -----------------------------------------------------
__global__ void k_pool(const int* __restrict__ batch, int n) {
    __shared__ float sm[NG * F];
    __shared__ float smc[NG];
    int tid = threadIdx.x;                 // 256
    for (int i = tid; i < NG * F; i += 256) sm[i] = 0.f;
    if (tid < NG) smc[tid] = 0.f;
    __syncthreads();

    int per = (n + gridDim.x - 1) / gridDim.x;
    int b0 = blockIdx.x * per;
    int b1 = min(n, b0 + per);
    for (int i = b0 * 64 + tid; i < b1 * 64; i += 256) {
        int node = i >> 6, f = i & 63;
        atomicAdd(&sm[batch[node] * 64 + f], g_h[i]);
    }
    for (int node = b0 + tid; node < b1; node += 256)
        atomicAdd(&smc[batch[node]], 1.0f);
    __syncthreads();

    for (int i = tid; i < NG * F; i += 256)
        if (sm[i] != 0.f) atomicAdd(&g_pool[i], sm[i]);
    if (tid < NG && smc[tid] != 0.f) atomicAdd(&g_cnt[tid], smc[tid]);
}

// ---------------- head: mean, LayerNorm, MLP ---------------------------------
__global__ void k_head(const float* __restrict__ lnw, const float* __restrict__ lnb,
                       const float* __restrict__ P1w, const float* __restrict__ P1b,
                       const float* __restrict__ P2w, const float* __restrict__ P2b,
                       float* __restrict__ out) {
    __shared__ float z [NG * F];
    __shared__ float h1[NG * 128];
    int tid = threadIdx.x;           // 128

    if (tid < NG) {
        int g = tid;
        float c = fmaxf(g_cnt[g], 1.0f);
        float inv = 1.0f / c;
        float mu = 0.f;
        for (int f = 0; f < 64; f++) mu += g_pool[g * 64 + f];
        mu *= inv * (1.0f / 64.0f);
        float var = 0.f;
        for (int f = 0; f < 64; f++) {
            float d = g_pool[g * 64 + f] * inv - mu;
            var += d * d;
        }
        var *= (1.0f / 64.0f);
        float rs = rsqrtf(var + 1e-5f);
        for (int f = 0; f < 64; f++)
            z[g * 64 + f] = (g_pool[g * 64 + f] * inv - mu) * rs * lnw[f] + lnb[f];
    }
    __syncthreads();

    for (int idx = tid; idx < NG * 128; idx += 128) {
        int g = idx >> 7, j = idx & 127;
        float s = P1b[j];
        for (int k = 0; k < 64; k++) s += z[g * 64 + k] * P1w[k * 128 + j];
        h1[idx] = fmaxf(s, 0.f);
    }
    __syncthreads();

    {
        int g = tid >> 1, o = tid & 1;
        float s = P2b[o];
        for (int j = 0; j < 128; j++) s += h1[g * 128 + j] * P2w[j * 2 + o];
        out[g * 2 + o] = s;
    }
}

// ---------------- launch -----------------------------------------------------
extern "C" void kernel_launch(void* const* d_in, const int* in_sizes, int n_in,
                              void* d_out, int out_size) {
    const float* x     = (const float*)d_in[0];
    const int*   src   = (const int*)  d_in[1];
    const int*   dst   = (const int*)  d_in[2];
    const int*   batch = (const int*)  d_in[3];
    const float* W1_in = (const float*)d_in[4];
    const float* b1_in = (const float*)d_in[5];
    const float* W1_out= (const float*)d_in[6];
    const float* b1_out= (const float*)d_in[7];
    const float* W2_in = (const float*)d_in[8];
    const float* b2_in = (const float*)d_in[9];
    const float* W2_out= (const float*)d_in[10];
    const float* b2_out= (const float*)d_in[11];
    const float* W3_in = (const float*)d_in[12];
    const float* b3_in = (const float*)d_in[13];
    const float* W3_out= (const float*)d_in[14];
    const float* b3_out= (const float*)d_in[15];
    const float* ln_w  = (const float*)d_in[16];
    const float* ln_b  = (const float*)d_in[17];
    const float* P1_w  = (const float*)d_in[18];
    const float* P1_b  = (const float*)d_in[19];
    const float* P2_w  = (const float*)d_in[20];
    const float* P2_b  = (const float*)d_in[21];
    float* out = (float*)d_out;

    int n = in_sizes[0] / 64;   // 50000
    int e = in_sizes[1];        // 800000

    int ib = (n + 255) / 256;
    int eb4 = ((e + 3) / 4 + 255) / 256;
    k_init   <<<ib, 256>>>(n);
    k_count  <<<eb4, 256>>>(src, dst, e);
    k_offsets<<<ib, 256>>>(n);
    k_place  <<<eb4, 256>>>(src, dst, e);

    int gemmBlocks = (n + 63) / 64;
    int gathBlocks = (n * 32 + 255) / 256;

    // layer 1
    k_gemm  <<<gemmBlocks, 256>>>(x, W1_in, W1_out, n);
    k_gather<<<gathBlocks, 256>>>(b1_in, b1_out, n, 1);
    // layer 2
    k_gemm  <<<gemmBlocks, 256>>>(nullptr, W2_in, W2_out, n);
    k_gather<<<gathBlocks, 256>>>(b2_in, b2_out, n, 1);
    // layer 3
    k_gemm  <<<gemmBlocks, 256>>>(nullptr, W3_in, W3_out, n);
    k_gather<<<gathBlocks, 256>>>(b3_in, b3_out, n, 0);

    k_pool<<<128, 256>>>(batch, n);
    k_head<<<1, 128>>>(ln_w, ln_b, P1_w, P1_b, P2_w, P2_b, out);
}